// round 2
// baseline (speedup 1.0000x reference)
#include <cuda_runtime.h>
#include <math.h>

#define B 4
#define HW 48
#define PIX 2304        // 48*48
#define D 64
#define JH 46
#define C 2116          // 46*46
#define NSPLIT 4
#define KSEG (PIX/NSPLIT)   // 576

// ---------------- scratch (device globals; per-batch reuse => ~110MB total) ----------------
__device__ float d_bg[B*PIX*D];        // masked input (all batches, 2.4MB)
__device__ float d_ng[B*PIX];          // ||g_in pixel||^2
__device__ float d_nbg[B*PIX];         // ||bg pixel||^2
__device__ float d_wwd[B*PIX];         // 3x3 same-pad box sum of d_ng
__device__ float d_k1d[B*C];           // 3x3 valid box sum of d_nbg
__device__ float d_G[PIX*PIX];         // per-pixel gram (ONE batch, 21.2MB)
__device__ float d_Hh[HW*HW*JH*HW];    // y-diagonal 3-sum of G (one batch, 20.3MB)
__device__ float d_CA[PIX*C];          // attention weights (one batch, 19.5MB)
__device__ float d_Pm[HW*HW*HW*JH];    // y-diagonal 3-sum of CA (one batch, 20.3MB)
__device__ float d_CB[PIX*PIX];        // full diagonal box sum of CA (one batch, 21.2MB)
__device__ float d_aclp[NSPLIT][PIX*D];// K-split partials of CB @ bg (one batch, 2.4MB)

// ---------------- block reductions (256 threads, 8 warps) ----------------
__device__ __forceinline__ float blkSum(float v, volatile float* sh) {
    for (int o = 16; o; o >>= 1) v += __shfl_down_sync(0xffffffffu, v, o);
    int w = threadIdx.x >> 5;
    if ((threadIdx.x & 31) == 0) sh[w] = v;
    __syncthreads();
    if (threadIdx.x == 0) {
        float s = 0.f;
        for (int i = 0; i < 8; i++) s += sh[i];
        sh[0] = s;
    }
    __syncthreads();
    float r = sh[0];
    __syncthreads();
    return r;
}

__device__ __forceinline__ float blkMax(float v, volatile float* sh) {
    for (int o = 16; o; o >>= 1) v = fmaxf(v, __shfl_down_sync(0xffffffffu, v, o));
    int w = threadIdx.x >> 5;
    if ((threadIdx.x & 31) == 0) sh[w] = v;
    __syncthreads();
    if (threadIdx.x == 0) {
        float s = sh[0];
        for (int i = 1; i < 8; i++) s = fmaxf(s, sh[i]);
        sh[0] = s;
    }
    __syncthreads();
    float r = sh[0];
    __syncthreads();
    return r;
}

// ---------------- K1: bg + pixel norms (all batches) ----------------
__global__ void prep_kernel(const float* __restrict__ g_in,
                            const float* __restrict__ mask) {
    int pix = blockIdx.x * 4 + (threadIdx.x >> 6);   // 4 pixels per block
    int ch  = threadIdx.x & 63;
    float g = g_in[pix * D + ch];
    float m = mask[pix];
    float bgv = g * m;
    d_bg[pix * D + ch] = bgv;
    float ng = g * g, nb = bgv * bgv;
    for (int o = 16; o; o >>= 1) {
        ng += __shfl_down_sync(0xffffffffu, ng, o);
        nb += __shfl_down_sync(0xffffffffu, nb, o);
    }
    __shared__ float sng[8], snb[8];
    int w = threadIdx.x >> 5;
    if ((threadIdx.x & 31) == 0) { sng[w] = ng; snb[w] = nb; }
    __syncthreads();
    if (ch == 0) {   // lane 0 of even warp
        d_ng[pix]  = sng[w] + sng[w + 1];
        d_nbg[pix] = snb[w] + snb[w + 1];
    }
}

// ---------------- K2: box sums (all batches) ----------------
__global__ void box_kernel() {
    int idx = blockIdx.x * blockDim.x + threadIdx.x;
    if (idx >= B * PIX) return;
    int b = idx / PIX, p = idx % PIX;
    int y = p / HW, x = p % HW;
    float s = 0.f;
    for (int dy = 0; dy < 3; dy++)
        for (int dx = 0; dx < 3; dx++) {
            int yy = y + dy - 1, xx = x + dx - 1;
            if ((unsigned)yy < (unsigned)HW && (unsigned)xx < (unsigned)HW)
                s += d_ng[b * PIX + yy * HW + xx];
        }
    d_wwd[idx] = s;
    if (y < JH && x < JH) {
        float s2 = 0.f;
        for (int dy = 0; dy < 3; dy++)
            for (int dx = 0; dx < 3; dx++)
                s2 += d_nbg[b * PIX + (y + dy) * HW + (x + dx)];
        d_k1d[b * C + y * JH + x] = s2;
    }
}

// ---------------- K3: G = g_in @ bg^T (one batch) ----------------
__global__ void gemmG_kernel(const float* __restrict__ g_in, int b) {
    __shared__ float As[64][65];
    __shared__ float Bs[64][65];
    int pt = blockIdx.y * 64, qt = blockIdx.x * 64;
    const float* Ap = g_in + (size_t)b * PIX * D;
    const float* Bp = d_bg + (size_t)b * PIX * D;
    int tid = threadIdx.x;
    for (int i = tid; i < 4096; i += 256) {
        int r = i >> 6, c = i & 63;
        As[r][c] = Ap[(pt + r) * D + c];
        Bs[r][c] = Bp[(qt + r) * D + c];
    }
    __syncthreads();
    int ty = tid >> 4, tx = tid & 15;
    float acc[4][4] = {};
#pragma unroll 8
    for (int k = 0; k < 64; k++) {
        float a[4], bb[4];
#pragma unroll
        for (int i = 0; i < 4; i++) { a[i] = As[ty + 16 * i][k]; bb[i] = Bs[tx + 16 * i][k]; }
#pragma unroll
        for (int i = 0; i < 4; i++)
#pragma unroll
            for (int j = 0; j < 4; j++) acc[i][j] += a[i] * bb[j];
    }
#pragma unroll
    for (int i = 0; i < 4; i++)
#pragma unroll
        for (int j = 0; j < 4; j++)
            d_G[(size_t)(pt + ty + 16 * i) * PIX + qt + tx + 16 * j] = acc[i][j];
}

// ---------------- K4: H[y][px][jy][qx] = sum_dy G[(y+dy-1,px)][(jy+dy,qx)] ----------------
__global__ void hbuild_kernel() {
    int n = HW * HW * JH * HW;
    int idx = blockIdx.x * blockDim.x + threadIdx.x;
    if (idx >= n) return;
    int qx = idx % HW; int t = idx / HW;
    int jy = t % JH;   t /= JH;
    int px = t % HW;   int y = t / HW;
    float s = 0.f;
#pragma unroll
    for (int dy = 0; dy < 3; dy++) {
        int yy = y + dy - 1;
        if ((unsigned)yy < (unsigned)HW)
            s += d_G[(size_t)(yy * HW + px) * PIX + (jy + dy) * HW + qx];
    }
    d_Hh[idx] = s;
}

// ---------------- K5: fused CS row + stats + tanh + softmax -> CA ----------------
__global__ void row_kernel(int b) {
    __shared__ float rowbuf[C];
    __shared__ float red[8];
    int p = blockIdx.x;
    int y = p / HW, x = p % HW;
    int tid = threadIdx.x;
    float wv = d_wwd[b * PIX + p];

    // pass 1: CS via x-diagonal sum of H, DS1 = k1d + wwd - 2CS
    float s = 0.f;
    for (int j = tid; j < C; j += 256) {
        int jy = j / JH, jx = j - jy * JH;
        float cs = 0.f;
#pragma unroll
        for (int dx = 0; dx < 3; dx++) {
            int xx = x + dx - 1;
            if ((unsigned)xx < (unsigned)HW)
                cs += d_Hh[((y * HW + xx) * JH + jy) * HW + (jx + dx)];
        }
        float ds = d_k1d[b * C + j] + wv - 2.f * cs;
        rowbuf[j] = ds;
        s += ds;
    }
    float mu = blkSum(s, red) * (1.f / (float)C);

    // pass 2: variance (two-pass for accuracy)
    float s2 = 0.f;
    for (int j = tid; j < C; j += 256) { float d = rowbuf[j] - mu; s2 += d * d; }
    float var = blkSum(s2, red) * (1.f / (float)C);
    float inv_sd = rsqrtf(var);

    // pass 3: logits = -50*tanh((ds-mu)/sd), track max
    float mx = -1e30f;
    for (int j = tid; j < C; j += 256) {
        float l = -50.f * tanhf((rowbuf[j] - mu) * inv_sd);
        rowbuf[j] = l;
        mx = fmaxf(mx, l);
    }
    mx = blkMax(mx, red);

    // pass 4: exp + sum
    float se = 0.f;
    for (int j = tid; j < C; j += 256) {
        float e = __expf(rowbuf[j] - mx);
        rowbuf[j] = e;
        se += e;
    }
    float invZ = 1.f / blkSum(se, red);

    // pass 5: write CA
    float* ca = d_CA + (size_t)p * C;
    for (int j = tid; j < C; j += 256) ca[j] = rowbuf[j] * invZ;
}

// ---------------- K6: Pm[y][x][u][v] = sum_dy CA[(y+1-dy,x)][(u-dy,v)] ----------------
__global__ void pm_kernel() {
    int n = HW * HW * HW * JH;
    int idx = blockIdx.x * blockDim.x + threadIdx.x;
    if (idx >= n) return;
    int v = idx % JH; int t = idx / JH;
    int u = t % HW;   t /= HW;
    int x = t % HW;   int y = t / HW;
    float s = 0.f;
#pragma unroll
    for (int dy = 0; dy < 3; dy++) {
        int yy = y + 1 - dy, uu = u - dy;
        if ((unsigned)yy < (unsigned)HW && (unsigned)uu < (unsigned)JH)
            s += d_CA[(size_t)(yy * HW + x) * C + uu * JH + v];
    }
    d_Pm[idx] = s;
}

// ---------------- K7: CB[(y,x)][(u,v)] = sum_dx Pm[y][x+1-dx][u][v-dx] ----------------
__global__ void cb_kernel() {
    int n = PIX * PIX;
    int idx = blockIdx.x * blockDim.x + threadIdx.x;
    if (idx >= n) return;
    int v = idx % HW; int t = idx / HW;
    int u = t % HW;   t /= HW;
    int x = t % HW;   int y = t / HW;
    float s = 0.f;
#pragma unroll
    for (int dx = 0; dx < 3; dx++) {
        int xx = x + 1 - dx, vv = v - dx;
        if ((unsigned)xx < (unsigned)HW && (unsigned)vv < (unsigned)JH)
            s += d_Pm[(((size_t)y * HW + xx) * HW + u) * JH + vv];
    }
    d_CB[idx] = s;
}

// ---------------- K8: acl partials = CB @ bg (M=2304, N=64, K split 4x576) ----------------
__global__ void gemmCB_kernel(int b) {
    __shared__ float Acb[64][65];   // CB rows x k
    __shared__ float Bcb[64][65];   // k x d
    int ks = blockIdx.y;
    int mt = blockIdx.x * 64;
    const float* bgp = d_bg + (size_t)b * PIX * D;
    int tid = threadIdx.x;
    int ty = tid >> 4, tx = tid & 15;
    float acc[4][4] = {};
    int kbase = ks * KSEG;
    for (int kt = 0; kt < KSEG; kt += 64) {
        int k0 = kbase + kt;
        for (int i = tid; i < 4096; i += 256) {
            int r = i >> 6, c = i & 63;
            Acb[r][c] = d_CB[(size_t)(mt + r) * PIX + k0 + c];
            Bcb[r][c] = bgp[(k0 + r) * D + c];
        }
        __syncthreads();
#pragma unroll 8
        for (int k = 0; k < 64; k++) {
            float a[4], bb[4];
#pragma unroll
            for (int i = 0; i < 4; i++) { a[i] = Acb[ty + 16 * i][k]; bb[i] = Bcb[k][tx + 16 * i]; }
#pragma unroll
            for (int i = 0; i < 4; i++)
#pragma unroll
                for (int j = 0; j < 4; j++) acc[i][j] += a[i] * bb[j];
        }
        __syncthreads();
    }
    float* outp = d_aclp[ks];
#pragma unroll
    for (int i = 0; i < 4; i++)
#pragma unroll
        for (int j = 0; j < 4; j++)
            outp[(mt + ty + 16 * i) * D + tx + 16 * j] = acc[i][j];
}

// ---------------- K9: ACL + concat + W2 GEMM + ELU (one batch) ----------------
__global__ void final_kernel(const float* __restrict__ g_in,
                             const float* __restrict__ mask,
                             const float* __restrict__ W2,
                             const float* __restrict__ b2,
                             float* __restrict__ out, int b) {
    __shared__ float w2s[128 * 64];
    __shared__ float cats[4][128];
    int tid = threadIdx.x;
    int g = tid >> 6, dch = tid & 63;
    int pl  = blockIdx.x * 4 + g;        // pixel within batch
    int pix = b * PIX + pl;              // global pixel
    for (int i = tid; i < 128 * 64; i += 256) w2s[i] = W2[i];

    float gv = g_in[pix * D + dch];
    float m  = mask[pix];
    float a  = 0.f;
#pragma unroll
    for (int s = 0; s < NSPLIT; s++) a += d_aclp[s][pl * D + dch];
    float ACL = d_bg[pix * D + dch] + a * (1.f / 9.f) * (1.f - m);
    cats[g][dch]      = gv;
    cats[g][64 + dch] = ACL;
    __syncthreads();

    float acc = b2[dch];
#pragma unroll 16
    for (int k = 0; k < 128; k++) acc += cats[g][k] * w2s[k * 64 + dch];
    out[pix * D + dch] = acc > 0.f ? acc : expm1f(acc);
}

// ---------------- launch ----------------
extern "C" void kernel_launch(void* const* d_in, const int* in_sizes, int n_in,
                              void* d_out, int out_size) {
    const float* g_in = (const float*)d_in[0];
    const float* mask = (const float*)d_in[1];
    const float* W2   = (const float*)d_in[2];
    const float* b2   = (const float*)d_in[3];
    float* out = (float*)d_out;

    prep_kernel<<<B * PIX / 4, 256>>>(g_in, mask);
    box_kernel<<<(B * PIX + 255) / 256, 256>>>();

    for (int b = 0; b < B; b++) {
        gemmG_kernel<<<dim3(PIX / 64, PIX / 64), 256>>>(g_in, b);
        {
            int n = HW * HW * JH * HW;
            hbuild_kernel<<<(n + 255) / 256, 256>>>();
        }
        row_kernel<<<PIX, 256>>>(b);
        {
            int n = HW * HW * HW * JH;
            pm_kernel<<<(n + 255) / 256, 256>>>();
        }
        {
            int n = PIX * PIX;
            cb_kernel<<<(n + 255) / 256, 256>>>();
        }
        gemmCB_kernel<<<dim3(PIX / 64, NSPLIT), 256>>>(b);
        final_kernel<<<PIX / 4, 256>>>(g_in, mask, W2, b2, out, b);
    }
}